// round 1
// baseline (speedup 1.0000x reference)
#include <cuda_runtime.h>
#include <math.h>

#define B_    16
#define V_    128
#define T_    32
#define DIN_  64
#define HD_   128
#define HN_   32
#define DOUT_ 64
#define NTB   (T_*B_)      /* 512  */
#define NTBV  (NTB*V_)     /* 65536 */
#define E1S   132

// ---------------- scratch (static device arrays; no allocation in kernel_launch) ----------
__device__ float g_ai [NTBV*HD_];   // 33.5 MB
__device__ float g_bj [NTBV*HD_];   // 33.5 MB
__device__ float g_agg[NTBV*HD_];   // 33.5 MB
__device__ float g_m  [NTB*HD_];
__device__ float g_gi [NTB*3*HD_];
__device__ float g_y  [NTB*HD_];
__device__ float g_Wpa[DIN_*HD_];
__device__ float g_Wpb[DIN_*HD_];
__device__ float g_ba [HD_];
__device__ float g_bb [HD_];

// ---------------- K0: fold x@Wp+bp through W1a/W1b (affine fusion) ------------------------
// Wpa = Wp @ W1[:HD],  Wpb = Wp @ W1[HD:],  ba = bp@W1a + b1,  bb = bp@W1b
__global__ void k0_prep(const float* __restrict__ Wp, const float* __restrict__ bp,
                        const float* __restrict__ W1, const float* __restrict__ b1) {
    int r = blockIdx.x;              // 0..63: weight rows, 64: biases
    int which = threadIdx.x >> 7;    // 0 -> 'a', 1 -> 'b'
    int h = threadIdx.x & 127;
    if (r < DIN_) {
        float acc = 0.f;
        for (int c = 0; c < HD_; ++c)
            acc = fmaf(Wp[r*HD_ + c], W1[(which*HD_ + c)*HD_ + h], acc);
        (which ? g_Wpb : g_Wpa)[r*HD_ + h] = acc;
    } else {
        float acc = which ? 0.f : b1[h];
        for (int c = 0; c < HD_; ++c)
            acc = fmaf(bp[c], W1[(which*HD_ + c)*HD_ + h], acc);
        (which ? g_bb : g_ba)[h] = acc;
    }
}

// ---------------- K1: ai/bj = x @ Wpa/Wpb + ba/bb  (per (t,b) block, weights in smem) -----
__global__ __launch_bounds__(256) void k1_aibj(const float* __restrict__ x) {
    extern __shared__ float sm[];
    float* s_Wa = sm;              // 8192
    float* s_Wb = sm + 8192;       // 8192
    float* s_x  = sm + 16384;      // 64
    int tb = blockIdx.x;           // t*16 + b
    int b = tb & (B_-1), t = tb >> 4;
    int tid = threadIdx.x;
    for (int idx = tid; idx < DIN_*HD_; idx += 256) { s_Wa[idx] = g_Wpa[idx]; s_Wb[idx] = g_Wpb[idx]; }
    int which = tid >> 7, h = tid & 127;
    const float* sW = which ? s_Wb : s_Wa;
    float bias = which ? g_bb[h] : g_ba[h];
    float* dst = (which ? g_bj : g_ai) + (size_t)tb*V_*HD_ + h;
    __syncthreads();
    for (int i = 0; i < V_; ++i) {
        if (tid < DIN_) s_x[tid] = x[(((size_t)b*V_ + i)*T_ + t)*DIN_ + tid];
        __syncthreads();
        float a0 = bias, a1 = 0.f, a2 = 0.f, a3 = 0.f;
        #pragma unroll
        for (int d = 0; d < DIN_; d += 4) {
            a0 = fmaf(s_x[d  ], sW[(d  )*HD_ + h], a0);
            a1 = fmaf(s_x[d+1], sW[(d+1)*HD_ + h], a1);
            a2 = fmaf(s_x[d+2], sW[(d+2)*HD_ + h], a2);
            a3 = fmaf(s_x[d+3], sW[(d+3)*HD_ + h], a3);
        }
        dst[(size_t)i*HD_] = (a0+a1)+(a2+a3);
        __syncthreads();
    }
}

// ---------------- K2: THE HOT KERNEL ------------------------------------------------------
// per (t,b,i): agg[h] = sum_{j active} adj * relu( relu(ai_i + bj_j) @ W2 + b2 )[h]
// active-j compaction (adj is 0/1, ~50% dense), 64-row E1 chunks in smem,
// 4j x 8h register tiles, W2 resident in smem (float4 reads, conflict-free).
__global__ __launch_bounds__(256, 2) void k2_edge(const float* __restrict__ adj,
                                                  const float* __restrict__ W2,
                                                  const float* __restrict__ b2) {
    extern __shared__ float sm[];
    float* s_W2   = sm;                  // 16384
    float* s_E1   = sm + 16384;          // 64*132 = 8448
    float* s_part = s_E1 + 64*E1S;       // 16*132 = 2112 (also temp adj row)
    float* s_ai   = s_part + 16*E1S;     // 128
    float* s_b2   = s_ai + 128;          // 128
    float* s_adjw = s_b2 + 128;          // 128
    int*   s_idx  = (int*)(s_adjw + 128);// 128
    int*   s_nj   = s_idx + 128;         // 1

    int n  = blockIdx.x;
    int i  = n & (V_-1);
    int tb = n >> 7;                     // t*16 + b
    int b  = tb & (B_-1);
    int tid = threadIdx.x;

    const float4* W24 = (const float4*)W2;
    float4* sW24 = (float4*)s_W2;
    for (int idx = tid; idx < (HD_*HD_)/4; idx += 256) sW24[idx] = W24[idx];

    if (tid < 128) {
        s_ai[tid]   = g_ai[(size_t)n*HD_ + tid];
        s_b2[tid]   = b2[tid];
        s_part[tid] = adj[((size_t)(b*V_ + i))*V_ + tid];   // stage adj row
    }
    __syncthreads();
    if (tid == 0) {                      // deterministic compaction
        int c = 0;
        for (int j = 0; j < V_; ++j) {
            float w = s_part[j];
            if (w != 0.f) { s_idx[c] = j; s_adjw[c] = w; ++c; }
        }
        *s_nj = c;
    }
    __syncthreads();
    int nj = *s_nj;

    int th = tid & 15, tj = tid >> 4;
    float aggp[8];
    #pragma unroll
    for (int u = 0; u < 8; ++u) aggp[u] = 0.f;

    const float* bjbase = g_bj + (size_t)tb * V_ * HD_;

    for (int c0 = 0; c0 < nj; c0 += 64) {
        int cn = nj - c0; if (cn > 64) cn = 64;
        __syncthreads();
        // build compacted E1 chunk: relu(ai + bj)  (b1 folded into ai's bias)
        for (int idx = tid; idx < 64*HD_; idx += 256) {
            int r = idx >> 7, h = idx & 127;
            float v = 0.f;
            if (r < cn) {
                int j = s_idx[c0 + r];
                v = fmaxf(s_ai[h] + bjbase[(size_t)j*HD_ + h], 0.f);
            }
            s_E1[r*E1S + h] = v;
        }
        __syncthreads();
        int r0 = tj * 4;
        if (r0 < cn) {                   // skip fully-padded tiles
            float acc[4][8];
            #pragma unroll
            for (int r = 0; r < 4; ++r)
                #pragma unroll
                for (int u = 0; u < 8; ++u) acc[r][u] = 0.f;
            #pragma unroll 4
            for (int k = 0; k < HD_; ++k) {
                float4 wa = *(const float4*)(s_W2 + k*HD_ + th*8);
                float4 wb = *(const float4*)(s_W2 + k*HD_ + th*8 + 4);
                float e[4];
                #pragma unroll
                for (int r = 0; r < 4; ++r) e[r] = s_E1[(r0+r)*E1S + k];
                #pragma unroll
                for (int r = 0; r < 4; ++r) {
                    acc[r][0] = fmaf(e[r], wa.x, acc[r][0]);
                    acc[r][1] = fmaf(e[r], wa.y, acc[r][1]);
                    acc[r][2] = fmaf(e[r], wa.z, acc[r][2]);
                    acc[r][3] = fmaf(e[r], wa.w, acc[r][3]);
                    acc[r][4] = fmaf(e[r], wb.x, acc[r][4]);
                    acc[r][5] = fmaf(e[r], wb.y, acc[r][5]);
                    acc[r][6] = fmaf(e[r], wb.z, acc[r][6]);
                    acc[r][7] = fmaf(e[r], wb.w, acc[r][7]);
                }
            }
            #pragma unroll
            for (int r = 0; r < 4; ++r) {
                int cr = c0 + r0 + r;
                float w = (cr < nj) ? s_adjw[cr] : 0.f;   // gate padded rows
                #pragma unroll
                for (int u = 0; u < 8; ++u)
                    aggp[u] += w * fmaxf(acc[r][u] + s_b2[th*8 + u], 0.f);
            }
        }
    }
    __syncthreads();
    #pragma unroll
    for (int u = 0; u < 8; ++u) s_part[tj*E1S + th*8 + u] = aggp[u];
    __syncthreads();
    if (tid < 128) {
        float s = 0.f;
        #pragma unroll
        for (int q = 0; q < 16; ++q) s += s_part[q*E1S + tid];
        g_agg[(size_t)n*HD_ + tid] = s;
    }
}

// ---------------- K3: node MLP (2 layers) + mean over i, per (t,b) block ------------------
__global__ __launch_bounds__(128) void k3_node(const float* __restrict__ Wn1, const float* __restrict__ bn1,
                                               const float* __restrict__ Wn2, const float* __restrict__ bn2) {
    extern __shared__ float sm[];
    float* sW1   = sm;                 // 16384
    float* sW2   = sm + 16384;         // 16384
    float* s_row = sm + 32768;         // 128
    float* s_t1  = s_row + 128;        // 128
    float* s_mac = s_t1 + 128;         // 128
    int tb = blockIdx.x, tid = threadIdx.x;
    for (int idx = tid; idx < HD_*HD_; idx += 128) { sW1[idx] = Wn1[idx]; sW2[idx] = Wn2[idx]; }
    s_mac[tid] = 0.f;
    float br1 = bn1[tid], br2 = bn2[tid];
    __syncthreads();
    for (int i = 0; i < V_; ++i) {
        __syncthreads();
        s_row[tid] = g_agg[((size_t)tb*V_ + i)*HD_ + tid];
        __syncthreads();
        float a0 = br1, a1 = 0.f, a2 = 0.f, a3 = 0.f;
        #pragma unroll 8
        for (int k = 0; k < HD_; k += 4) {
            a0 = fmaf(s_row[k  ], sW1[(k  )*HD_ + tid], a0);
            a1 = fmaf(s_row[k+1], sW1[(k+1)*HD_ + tid], a1);
            a2 = fmaf(s_row[k+2], sW1[(k+2)*HD_ + tid], a2);
            a3 = fmaf(s_row[k+3], sW1[(k+3)*HD_ + tid], a3);
        }
        s_t1[tid] = fmaxf((a0+a1)+(a2+a3), 0.f);
        __syncthreads();
        float c0 = br2, c1 = 0.f, c2 = 0.f, c3 = 0.f;
        #pragma unroll 8
        for (int k = 0; k < HD_; k += 4) {
            c0 = fmaf(s_t1[k  ], sW2[(k  )*HD_ + tid], c0);
            c1 = fmaf(s_t1[k+1], sW2[(k+1)*HD_ + tid], c1);
            c2 = fmaf(s_t1[k+2], sW2[(k+2)*HD_ + tid], c2);
            c3 = fmaf(s_t1[k+3], sW2[(k+3)*HD_ + tid], c3);
        }
        s_mac[tid] += fmaxf((c0+c1)+(c2+c3), 0.f);
    }
    g_m[(size_t)tb*HD_ + tid] = s_mac[tid] * (1.0f/(float)V_);
}

// ---------------- K4a: in-place cumsum over t ---------------------------------------------
__global__ void k4a_cumsum() {
    int gid = blockIdx.x * 1024 + threadIdx.x;   // 2048 total = B*HD
    int b = gid >> 7, h = gid & 127;
    float run = 0.f;
    for (int t = 0; t < T_; ++t) {
        size_t idx = ((size_t)t*B_ + b)*HD_ + h;
        run += g_m[idx];
        g_m[idx] = run;
    }
}

// ---------------- K4b: GRU input gates gi = cum @ Wih^T + bih -----------------------------
__global__ __launch_bounds__(384) void k4b_gi(const float* __restrict__ Wih, const float* __restrict__ bih) {
    __shared__ float s_c[128];
    int tb = blockIdx.x, tid = threadIdx.x;
    if (tid < 128) s_c[tid] = g_m[(size_t)tb*HD_ + tid];
    __syncthreads();
    float a0 = bih[tid], a1 = 0.f, a2 = 0.f, a3 = 0.f;
    const float* wr = Wih + (size_t)tid*HD_;
    #pragma unroll 8
    for (int k = 0; k < HD_; k += 4) {
        a0 = fmaf(s_c[k  ], wr[k  ], a0);
        a1 = fmaf(s_c[k+1], wr[k+1], a1);
        a2 = fmaf(s_c[k+2], wr[k+2], a2);
        a3 = fmaf(s_c[k+3], wr[k+3], a3);
    }
    g_gi[(size_t)tb*3*HD_ + tid] = (a0+a1)+(a2+a3);
}

// ---------------- K5: GRU, batch 16 only (HN broadcast exploited) -------------------------
__global__ __launch_bounds__(384) void k5_gru(const float* __restrict__ Whh, const float* __restrict__ bhh) {
    extern __shared__ float sm[];
    float* s_W  = sm;                    // 384*129 (padded, conflict-free)
    float* s_h  = sm + 384*129;          // 128
    float* s_gh = s_h + 128;             // 384
    int b = blockIdx.x, tid = threadIdx.x;
    for (int idx = tid; idx < 384*HD_; idx += 384) {
        int g = idx >> 7, k = idx & 127;
        s_W[g*129 + k] = Whh[idx];
    }
    float bh = bhh[tid];
    if (tid < 128) s_h[tid] = 0.f;
    __syncthreads();
    const float* wr = s_W + tid*129;
    for (int t = 0; t < T_; ++t) {
        float a0 = bh, a1 = 0.f, a2 = 0.f, a3 = 0.f;
        #pragma unroll 8
        for (int k = 0; k < HD_; k += 4) {
            a0 = fmaf(s_h[k  ], wr[k  ], a0);
            a1 = fmaf(s_h[k+1], wr[k+1], a1);
            a2 = fmaf(s_h[k+2], wr[k+2], a2);
            a3 = fmaf(s_h[k+3], wr[k+3], a3);
        }
        s_gh[tid] = (a0+a1)+(a2+a3);
        __syncthreads();
        if (tid < 128) {
            size_t row = ((size_t)t*B_ + b)*3*HD_;
            float r  = 1.f/(1.f + expf(-(g_gi[row +        tid] + s_gh[tid])));
            float z  = 1.f/(1.f + expf(-(g_gi[row + HD_ +  tid] + s_gh[HD_ + tid])));
            float nn = tanhf(g_gi[row + 2*HD_ + tid] + r*s_gh[2*HD_ + tid]);
            float hp = s_h[tid];
            float hv = (1.f - z)*nn + z*hp;
            s_h[tid] = hv;
            g_y[((size_t)t*B_ + b)*HD_ + tid] = hv;
        }
        __syncthreads();
    }
}

// ---------------- K6: output projection + HN broadcast ------------------------------------
__global__ __launch_bounds__(256) void k6_out(const float* __restrict__ Wo, const float* __restrict__ bo,
                                              float* __restrict__ out) {
    __shared__ float s_y[128];
    __shared__ float s_o[64];
    int bt = blockIdx.x;
    int b = bt >> 5, t = bt & 31;
    int tid = threadIdx.x;
    if (tid < 128) s_y[tid] = g_y[((size_t)t*B_ + b)*HD_ + tid];
    __syncthreads();
    if (tid < DOUT_) {
        float a0 = bo[tid], a1 = 0.f, a2 = 0.f, a3 = 0.f;
        #pragma unroll 8
        for (int h = 0; h < HD_; h += 4) {
            a0 = fmaf(s_y[h  ], Wo[(h  )*DOUT_ + tid], a0);
            a1 = fmaf(s_y[h+1], Wo[(h+1)*DOUT_ + tid], a1);
            a2 = fmaf(s_y[h+2], Wo[(h+2)*DOUT_ + tid], a2);
            a3 = fmaf(s_y[h+3], Wo[(h+3)*DOUT_ + tid], a3);
        }
        s_o[tid] = (a0+a1)+(a2+a3);
    }
    __syncthreads();
    for (int idx = tid; idx < HN_*DOUT_; idx += 256) {
        int hn = idx >> 6, d = idx & 63;
        out[(((size_t)b*HN_ + hn)*T_ + t)*DOUT_ + d] = s_o[d];
    }
}

// ---------------- launch ------------------------------------------------------------------
extern "C" void kernel_launch(void* const* d_in, const int* in_sizes, int n_in,
                              void* d_out, int out_size) {
    const float* x   = (const float*)d_in[0];
    const float* adj = (const float*)d_in[1];
    const float* Wp  = (const float*)d_in[2];
    const float* bp  = (const float*)d_in[3];
    const float* W1  = (const float*)d_in[4];
    const float* b1  = (const float*)d_in[5];
    const float* W2  = (const float*)d_in[6];
    const float* b2  = (const float*)d_in[7];
    const float* Wn1 = (const float*)d_in[8];
    const float* bn1 = (const float*)d_in[9];
    const float* Wn2 = (const float*)d_in[10];
    const float* bn2 = (const float*)d_in[11];
    const float* Wih = (const float*)d_in[12];
    const float* Whh = (const float*)d_in[13];
    const float* bih = (const float*)d_in[14];
    const float* bhh = (const float*)d_in[15];
    const float* Wo  = (const float*)d_in[16];
    const float* bo  = (const float*)d_in[17];
    float* out = (float*)d_out;

    size_t smem1 = (size_t)(16384 + 64) * sizeof(float);                 //  65,792 B
    size_t smem2 = (size_t)(16384 + 64*E1S + 16*E1S + 3*128 + 129) * sizeof(float); // ~109,844 B
    size_t smem3 = (size_t)(32768 + 3*128) * sizeof(float);              // 132,608 B
    size_t smem5 = (size_t)(384*129 + 128 + 384) * sizeof(float);        // 200,192 B

    cudaFuncSetAttribute(k1_aibj, cudaFuncAttributeMaxDynamicSharedMemorySize, (int)smem1);
    cudaFuncSetAttribute(k2_edge, cudaFuncAttributeMaxDynamicSharedMemorySize, (int)smem2);
    cudaFuncSetAttribute(k3_node, cudaFuncAttributeMaxDynamicSharedMemorySize, (int)smem3);
    cudaFuncSetAttribute(k5_gru,  cudaFuncAttributeMaxDynamicSharedMemorySize, (int)smem5);

    k0_prep  <<<DIN_ + 1, 256>>>(Wp, bp, W1, b1);
    k1_aibj  <<<NTB, 256, smem1>>>(x);
    k2_edge  <<<NTBV, 256, smem2>>>(adj, W2, b2);
    k3_node  <<<NTB, 128, smem3>>>(Wn1, bn1, Wn2, bn2);
    k4a_cumsum<<<2, 1024>>>();
    k4b_gi   <<<NTB, 384>>>(Wih, bih);
    k5_gru   <<<B_, 384, smem5>>>(Whh, bhh);
    k6_out   <<<B_*T_, 256>>>(Wo, bo, out);
}

// round 4
// speedup vs baseline: 3.8998x; 3.8998x over previous
#include <cuda_runtime.h>
#include <cuda_bf16.h>
#include <math.h>
#include <stdint.h>

#define B_    16
#define V_    128
#define T_    32
#define DIN_  64
#define HD_   128
#define HN_   32
#define DOUT_ 64
#define NTB   (T_*B_)      /* 512  */
#define NTBV  (NTB*V_)     /* 65536 */
#define WS    136          /* smem row stride in bf16 elements */
#define K2GRID 148
#define K3GRID 148

// ---------------- scratch ----------------------------------------------------------------
__device__ float          g_ai  [NTBV*HD_];
__device__ __nv_bfloat16  g_bjh [NTBV*HD_];
__device__ __nv_bfloat16  g_aggh[NTBV*HD_];
__device__ float g_m  [NTB*HD_];
__device__ float g_gi [NTB*3*HD_];
__device__ float g_y  [NTB*HD_];
__device__ float g_Wpa[DIN_*HD_];
__device__ float g_Wpb[DIN_*HD_];
__device__ float g_ba [HD_];
__device__ float g_bb [HD_];

// ---------------- helpers -----------------------------------------------------------------
__device__ __forceinline__ uint32_t smem_u32(const void* p) {
    uint32_t a;
    asm("{ .reg .u64 t; cvta.to.shared.u64 t, %1; cvt.u32.u64 %0, t; }" : "=r"(a) : "l"(p));
    return a;
}
__device__ __forceinline__ void ldmat_x4(uint32_t& a0, uint32_t& a1, uint32_t& a2, uint32_t& a3, uint32_t addr) {
    asm volatile("ldmatrix.sync.aligned.m8n8.x4.shared.b16 {%0,%1,%2,%3}, [%4];"
        : "=r"(a0), "=r"(a1), "=r"(a2), "=r"(a3) : "r"(addr));
}
__device__ __forceinline__ void mma_bf16(float* c, uint32_t a0, uint32_t a1, uint32_t a2, uint32_t a3,
                                         uint32_t b0, uint32_t b1) {
    asm volatile("mma.sync.aligned.m16n8k16.row.col.f32.bf16.bf16.f32 "
        "{%0,%1,%2,%3}, {%4,%5,%6,%7}, {%8,%9}, {%0,%1,%2,%3};"
        : "+f"(c[0]), "+f"(c[1]), "+f"(c[2]), "+f"(c[3])
        : "r"(a0), "r"(a1), "r"(a2), "r"(a3), "r"(b0), "r"(b1));
}
__device__ __forceinline__ uint32_t pack_hi(float w0, float w1) {
    __nv_bfloat162 p = __float22bfloat162_rn(make_float2(w0, w1));
    return *(uint32_t*)&p;
}
__device__ __forceinline__ uint32_t pack_lo(float w0, float w1) {
    __nv_bfloat16 h0 = __float2bfloat16(w0), h1 = __float2bfloat16(w1);
    float l0 = w0 - __bfloat162float(h0), l1 = w1 - __bfloat162float(h1);
    __nv_bfloat162 p = __float22bfloat162_rn(make_float2(l0, l1));
    return *(uint32_t*)&p;
}

// ---------------- K0: fold x@Wp+bp through W1a/W1b ---------------------------------------
__global__ void k0_prep(const float* __restrict__ Wp, const float* __restrict__ bp,
                        const float* __restrict__ W1, const float* __restrict__ b1) {
    int r = blockIdx.x;
    int which = threadIdx.x >> 7;
    int h = threadIdx.x & 127;
    if (r < DIN_) {
        float acc = 0.f;
        for (int c = 0; c < HD_; ++c)
            acc = fmaf(Wp[r*HD_ + c], W1[(which*HD_ + c)*HD_ + h], acc);
        (which ? g_Wpb : g_Wpa)[r*HD_ + h] = acc;
    } else {
        float acc = which ? 0.f : b1[h];
        for (int c = 0; c < HD_; ++c)
            acc = fmaf(bp[c], W1[(which*HD_ + c)*HD_ + h], acc);
        (which ? g_bb : g_ba)[h] = acc;
    }
}

// ---------------- K1: ai fp32 / bj bf16 = x @ Wpa/Wpb + bias ------------------------------
__global__ __launch_bounds__(256) void k1_aibj(const float* __restrict__ x) {
    extern __shared__ float sm[];
    float* s_Wa = sm;
    float* s_Wb = sm + 8192;
    float* s_x  = sm + 16384;
    int tb = blockIdx.x;
    int b = tb & (B_-1), t = tb >> 4;
    int tid = threadIdx.x;
    for (int idx = tid; idx < DIN_*HD_; idx += 256) { s_Wa[idx] = g_Wpa[idx]; s_Wb[idx] = g_Wpb[idx]; }
    int which = tid >> 7, h = tid & 127;
    const float* sW = which ? s_Wb : s_Wa;
    float bias = which ? g_bb[h] : g_ba[h];
    __syncthreads();
    for (int i = 0; i < V_; ++i) {
        if (tid < DIN_) s_x[tid] = x[(((size_t)b*V_ + i)*T_ + t)*DIN_ + tid];
        __syncthreads();
        float a0 = bias, a1 = 0.f, a2 = 0.f, a3 = 0.f;
        #pragma unroll
        for (int d = 0; d < DIN_; d += 4) {
            a0 = fmaf(s_x[d  ], sW[(d  )*HD_ + h], a0);
            a1 = fmaf(s_x[d+1], sW[(d+1)*HD_ + h], a1);
            a2 = fmaf(s_x[d+2], sW[(d+2)*HD_ + h], a2);
            a3 = fmaf(s_x[d+3], sW[(d+3)*HD_ + h], a3);
        }
        float v = (a0+a1)+(a2+a3);
        size_t o = (size_t)tb*V_*HD_ + (size_t)i*HD_ + h;
        if (which) g_bjh[o] = __float2bfloat16(v);
        else       g_ai [o] = v;
        __syncthreads();
    }
}

// ---------------- K2: warp-MMA edge MLP, split-weight, D[h,j] layout ----------------------
// A = W2^T (hi+lo bf16 register frags, per-warp h-tile), B = E1 rows=j via ldmatrix.
// agg[i,h] = sum_j adjw[j] * relu(D[h,j] + b2[h]); skipped/padded j gated by adjw=0.
__global__ __launch_bounds__(512, 1) void k2_edge_mma(const float* __restrict__ adj,
                                                      const float* __restrict__ W2,
                                                      const float* __restrict__ b2) {
    __shared__ __nv_bfloat16 sE[128*WS];
    __shared__ float s_ai[128], s_adjw[128], s_red[128], s_b2[128];
    __shared__ int s_idx[128], s_w[4];

    int tid = threadIdx.x, lane = tid & 31, wid = tid >> 5;
    int ht = wid >> 1, wp = wid & 1;
    int g = lane >> 2, tig = lane & 3;
    int h0 = ht*16 + g, h1 = h0 + 8;

    // ---- extract register-resident A fragments (W2^T hi/lo), once ----
    uint32_t Ahi[8][4], Alo[8][4];
    #pragma unroll
    for (int ks = 0; ks < 8; ++ks) {
        #pragma unroll
        for (int f = 0; f < 4; ++f) {
            int row = (f & 1) ? h1 : h0;
            int kb  = ks*16 + tig*2 + ((f >> 1) ? 8 : 0);
            float w0 = W2[kb*HD_ + row];
            float w1 = W2[(kb+1)*HD_ + row];
            Ahi[ks][f] = pack_hi(w0, w1);
            Alo[ks][f] = pack_lo(w0, w1);
        }
    }
    if (tid < 128) s_b2[tid] = b2[tid];
    // zero sE once (avoid NaN garbage feeding gated MMAs)
    for (int idx = tid; idx < 128*WS/2; idx += 512) ((uint32_t*)sE)[idx] = 0u;
    __syncthreads();

    uint32_t sE_base = smem_u32(sE);

    for (int n = blockIdx.x; n < NTBV; n += K2GRID) {
        int i  = n & (V_-1);
        int tb = n >> 7;
        int b  = tb & (B_-1);

        // ---- stage + ballot compaction ----
        float adjv = 0.f; bool act = false; unsigned mask = 0;
        if (tid < 128) {
            s_red[tid]  = 0.f;
            s_adjw[tid] = 0.f;
            s_ai[tid]   = g_ai[(size_t)n*HD_ + tid];
            adjv = adj[((size_t)(b*V_ + i))*V_ + tid];
            act = (adjv != 0.f);
            mask = __ballot_sync(0xffffffffu, act);
            if (lane == 0) s_w[wid] = __popc(mask);
        }
        __syncthreads();
        int nj = s_w[0] + s_w[1] + s_w[2] + s_w[3];
        if (tid < 128 && act) {
            int off = 0;
            #pragma unroll
            for (int q = 0; q < 4; ++q) if (q < wid) off += s_w[q];
            int pos = off + __popc(mask & ((1u << lane) - 1u));
            s_idx[pos] = tid; s_adjw[pos] = adjv;
        }
        __syncthreads();

        // ---- build E1 rows (compacted j): relu(ai + bj) bf16; stale rows gated by adjw=0 ----
        const __nv_bfloat16* bjb = g_bjh + (size_t)tb * V_ * HD_;
        #pragma unroll
        for (int q = 0; q < 4; ++q) {
            int cid = tid + q*512;
            int r = cid >> 4, c0 = (cid & 15)*8;
            if (r < nj) {
                int j = s_idx[r];
                uint4 u = *(const uint4*)(bjb + (size_t)j*HD_ + c0);
                float2 f0 = __bfloat1622float2(*(__nv_bfloat162*)&u.x);
                float2 f1 = __bfloat1622float2(*(__nv_bfloat162*)&u.y);
                float2 f2 = __bfloat1622float2(*(__nv_bfloat162*)&u.z);
                float2 f3 = __bfloat1622float2(*(__nv_bfloat162*)&u.w);
                f0.x = fmaxf(f0.x + s_ai[c0+0], 0.f); f0.y = fmaxf(f0.y + s_ai[c0+1], 0.f);
                f1.x = fmaxf(f1.x + s_ai[c0+2], 0.f); f1.y = fmaxf(f1.y + s_ai[c0+3], 0.f);
                f2.x = fmaxf(f2.x + s_ai[c0+4], 0.f); f2.y = fmaxf(f2.y + s_ai[c0+5], 0.f);
                f3.x = fmaxf(f3.x + s_ai[c0+6], 0.f); f3.y = fmaxf(f3.y + s_ai[c0+7], 0.f);
                __nv_bfloat162 o0 = __float22bfloat162_rn(f0);
                __nv_bfloat162 o1 = __float22bfloat162_rn(f1);
                __nv_bfloat162 o2 = __float22bfloat162_rn(f2);
                __nv_bfloat162 o3 = __float22bfloat162_rn(f3);
                uint4 ov;
                ov.x = *(uint32_t*)&o0; ov.y = *(uint32_t*)&o1;
                ov.z = *(uint32_t*)&o2; ov.w = *(uint32_t*)&o3;
                *(uint4*)(sE + r*WS + c0) = ov;
            }
        }
        __syncthreads();

        // ---- MMA: warp = (h-tile ht) x (jtp = wp, wp+2, wp+4, wp+6) ----
        float c[8][4];
        #pragma unroll
        for (int jg = 0; jg < 8; ++jg)
            #pragma unroll
            for (int e = 0; e < 4; ++e) c[jg][e] = 0.f;

        #pragma unroll
        for (int ji = 0; ji < 4; ++ji) {
            int jtp = wp + 2*ji;
            int jbase = jtp * 16;
            if (jbase < nj) {
                bool odd = (jbase + 8) < nj;
                uint32_t baddr = sE_base + (uint32_t)(((jbase + (lane & 15))*WS + (lane >> 4)*8) * 2);
                #pragma unroll
                for (int ks = 0; ks < 8; ++ks) {
                    uint32_t r0, r1, r2, r3;
                    ldmat_x4(r0, r1, r2, r3, baddr + ks*32);
                    mma_bf16(c[2*ji], Ahi[ks][0], Ahi[ks][1], Ahi[ks][2], Ahi[ks][3], r0, r2);
                    mma_bf16(c[2*ji], Alo[ks][0], Alo[ks][1], Alo[ks][2], Alo[ks][3], r0, r2);
                    if (odd) {
                        mma_bf16(c[2*ji+1], Ahi[ks][0], Ahi[ks][1], Ahi[ks][2], Ahi[ks][3], r1, r3);
                        mma_bf16(c[2*ji+1], Alo[ks][0], Alo[ks][1], Alo[ks][2], Alo[ks][3], r1, r3);
                    }
                }
            }
        }

        // ---- epilogue: per-lane j-reduction, tig shuffle, 2 atomics per h ----
        {
            float bh0 = s_b2[h0], bh1 = s_b2[h1];
            float p0 = 0.f, p1 = 0.f;
            #pragma unroll
            for (int jg = 0; jg < 8; ++jg) {
                int jtp = wp + 2*(jg >> 1);
                int j0 = jtp*16 + (jg & 1)*8 + tig*2;
                float w0 = s_adjw[j0], w1 = s_adjw[j0+1];
                p0 += w0*fmaxf(c[jg][0]+bh0, 0.f) + w1*fmaxf(c[jg][1]+bh0, 0.f);
                p1 += w0*fmaxf(c[jg][2]+bh1, 0.f) + w1*fmaxf(c[jg][3]+bh1, 0.f);
            }
            p0 += __shfl_xor_sync(0xffffffffu, p0, 1);
            p0 += __shfl_xor_sync(0xffffffffu, p0, 2);
            p1 += __shfl_xor_sync(0xffffffffu, p1, 1);
            p1 += __shfl_xor_sync(0xffffffffu, p1, 2);
            if (tig == 0) {
                atomicAdd(&s_red[h0], p0);
                atomicAdd(&s_red[h1], p1);
            }
        }
        __syncthreads();
        if (tid < 128) g_aggh[(size_t)n*HD_ + tid] = __float2bfloat16(s_red[tid]);
        __syncthreads();
    }
}

// ---------------- K3: warp-MMA node MLP (2 layers, split weights) + mean ------------------
__global__ __launch_bounds__(512, 1) void k3_node_mma(const float* __restrict__ Wn1, const float* __restrict__ bn1,
                                                      const float* __restrict__ Wn2, const float* __restrict__ bn2) {
    extern __shared__ char smraw[];
    __nv_bfloat16* sA   = (__nv_bfloat16*)smraw;          // 128*WS
    __nv_bfloat16* sT   = sA + 128*WS;
    __nv_bfloat16* sW1h = sT + 128*WS;                    // Wn1^T hi: [n][k]
    __nv_bfloat16* sW1l = sW1h + 128*WS;
    __nv_bfloat16* sW2h = sW1l + 128*WS;
    __nv_bfloat16* sW2l = sW2h + 128*WS;
    float* s_red = (float*)(sW2l + 128*WS);
    float* s_b1  = s_red + 128;
    float* s_b2  = s_b1 + 128;

    int tid = threadIdx.x, lane = tid & 31, wid = tid >> 5;
    int wm = wid & 3, wn = wid >> 2;           // 4 m-parity x 4 n-groups(32 cols)
    int g = lane >> 2, tig = lane & 3;

    // stage transposed split weights: sW[n*WS + k] = W[k*128 + n]
    for (int idx = tid; idx < HD_*HD_; idx += 512) {
        int nn = idx >> 7, k = idx & 127;
        float w1 = Wn1[k*HD_ + nn];
        float w2 = Wn2[k*HD_ + nn];
        __nv_bfloat16 h1v = __float2bfloat16(w1), h2v = __float2bfloat16(w2);
        sW1h[nn*WS + k] = h1v;
        sW1l[nn*WS + k] = __float2bfloat16(w1 - __bfloat162float(h1v));
        sW2h[nn*WS + k] = h2v;
        sW2l[nn*WS + k] = __float2bfloat16(w2 - __bfloat162float(h2v));
    }
    if (tid < 128) { s_b1[tid] = bn1[tid]; s_b2[tid] = bn2[tid]; }
    __syncthreads();

    uint32_t sA_base  = smem_u32(sA);
    uint32_t sT_base  = smem_u32(sT);
    uint32_t sW1h_b = smem_u32(sW1h), sW1l_b = smem_u32(sW1l);
    uint32_t sW2h_b = smem_u32(sW2h), sW2l_b = smem_u32(sW2l);

    for (int tb = blockIdx.x; tb < NTB; tb += K3GRID) {
        {
            const uint4* src = (const uint4*)(g_aggh + (size_t)tb*V_*HD_);
            #pragma unroll
            for (int q = 0; q < 4; ++q) {
                int cid = tid + q*512;
                int r = cid >> 4, c0 = (cid & 15)*8;
                *(uint4*)(sA + r*WS + c0) = src[cid];
            }
        }
        if (tid < 128) s_red[tid] = 0.f;
        __syncthreads();

        // ================= layer 1: sT = relu(sA @ Wn1 + b1) =================
        {
            float c[2][4][4];
            #pragma unroll
            for (int m = 0; m < 2; ++m)
                #pragma unroll
                for (int nt = 0; nt < 4; ++nt)
                    #pragma unroll
                    for (int e = 0; e < 4; ++e) c[m][nt][e] = 0.f;
            #pragma unroll
            for (int ks = 0; ks < 8; ++ks) {
                uint32_t koff = (uint32_t)((ks*16 + (lane >> 4)*8) * 2);
                uint32_t rsel = (uint32_t)((lane & 15) * WS * 2);
                uint32_t bh0[4], bh1[4], bl0[4], bl1[4];
                ldmat_x4(bh0[0], bh0[1], bh0[2], bh0[3], sW1h_b + (uint32_t)((wn*32)*WS*2) + rsel + koff);
                ldmat_x4(bh1[0], bh1[1], bh1[2], bh1[3], sW1h_b + (uint32_t)((wn*32+16)*WS*2) + rsel + koff);
                ldmat_x4(bl0[0], bl0[1], bl0[2], bl0[3], sW1l_b + (uint32_t)((wn*32)*WS*2) + rsel + koff);
                ldmat_x4(bl1[0], bl1[1], bl1[2], bl1[3], sW1l_b + (uint32_t)((wn*32+16)*WS*2) + rsel + koff);
                #pragma unroll
                for (int m = 0; m < 2; ++m) {
                    int m0 = (wm + 4*m) * 16;
                    uint32_t a0, a1, a2, a3;
                    ldmat_x4(a0, a1, a2, a3, sA_base + (uint32_t)(((m0 + (lane & 15))*WS)*2) + koff);
                    mma_bf16(c[m][0], a0,a1,a2,a3, bh0[0], bh0[2]);
                    mma_bf16(c[m][0], a0,a1,a2,a3, bl0[0], bl0[2]);
                    mma_bf16(c[m][1], a0,a1,a2,a3, bh0[1], bh0[3]);
                    mma_bf16(c[m][1], a0,a1,a2,a3, bl0[1], bl0[3]);
                    mma_bf16(c[m][2], a0,a1,a2,a3, bh1[0], bh1[2]);
                    mma_bf16(c[m][2], a0,a1,a2,a3, bl1[0], bl1[2]);
                    mma_bf16(c[m][3], a0,a1,a2,a3, bh1[1], bh1[3]);
                    mma_bf16(c[m][3], a0,a1,a2,a3, bl1[1], bl1[3]);
                }
            }
            #pragma unroll
            for (int m = 0; m < 2; ++m) {
                int r = (wm + 4*m)*16 + g;
                #pragma unroll
                for (int nt = 0; nt < 4; ++nt) {
                    int n0 = wn*32 + nt*8 + tig*2;
                    float v0 = fmaxf(c[m][nt][0] + s_b1[n0],   0.f);
                    float v1 = fmaxf(c[m][nt][1] + s_b1[n0+1], 0.f);
                    float v2 = fmaxf(c[m][nt][2] + s_b1[n0],   0.f);
                    float v3 = fmaxf(c[m][nt][3] + s_b1[n0+1], 0.f);
                    *(uint32_t*)((uint16_t*)sT + r*WS + n0)     = pack_hi(v0, v1);
                    *(uint32_t*)((uint16_t*)sT + (r+8)*WS + n0) = pack_hi(v2, v3);
                }
            }
        }
        __syncthreads();

        // ================= layer 2 + mean over rows =================
        {
            float c[2][4][4];
            #pragma unroll
            for (int m = 0; m < 2; ++m)
                #pragma unroll
                for (int nt = 0; nt < 4; ++nt)
                    #pragma unroll
                    for (int e = 0; e < 4; ++e) c[m][nt][e] = 0.f;
            #pragma unroll
            for (int ks = 0; ks < 8; ++ks) {
                uint32_t koff = (uint32_t)((ks*16 + (lane >> 4)*8) * 2);
                uint32_t rsel = (uint32_t)((lane & 15) * WS * 2);
                uint32_t bh0[4], bh1[4], bl0[4], bl1[4];
                ldmat_x4(bh0[0], bh0[1], bh0[2], bh0[3], sW2h_b + (uint32_t)((wn*32)*WS*2) + rsel + koff);
                ldmat_x4(bh1[0], bh1[1], bh1[2], bh1[3], sW2h_b + (uint32_t)((wn*32+16)*WS*2) + rsel + koff);
                ldmat_x4(bl0[0], bl0[1], bl0[2], bl0[3], sW2l_b + (uint32_t)((wn*32)*WS*2) + rsel + koff);
                ldmat_x4(bl1[0], bl1[1], bl1[2], bl1[3], sW2l_b + (uint32_t)((wn*32+16)*WS*2) + rsel + koff);
                #pragma unroll
                for (int m = 0; m < 2; ++m) {
                    int m0 = (wm + 4*m) * 16;
                    uint32_t a0, a1, a2, a3;
                    ldmat_x4(a0, a1, a2, a3, sT_base + (uint32_t)(((m0 + (lane & 15))*WS)*2) + koff);
                    mma_bf16(c[m][0], a0,a1,a2,a3, bh0[0], bh0[2]);
                    mma_bf16(c[m][0], a0,a1,a2,a3, bl0[0], bl0[2]);
                    mma_bf16(c[m][1], a0,a1,a2,a3, bh0[1], bh0[3]);
                    mma_bf16(c[m][1], a0,a1,a2,a3, bl0[1], bl0[3]);
                    mma_bf16(c[m][2], a0,a1,a2,a3, bh1[0], bh1[2]);
                    mma_bf16(c[m][2], a0,a1,a2,a3, bl1[0], bl1[2]);
                    mma_bf16(c[m][3], a0,a1,a2,a3, bh1[1], bh1[3]);
                    mma_bf16(c[m][3], a0,a1,a2,a3, bl1[1], bl1[3]);
                }
            }
            #pragma unroll
            for (int nt = 0; nt < 4; ++nt) {
                int n0 = wn*32 + nt*8 + tig*2;
                float bh0 = s_b2[n0], bh1 = s_b2[n0+1];
                float p0 = 0.f, p1 = 0.f;
                #pragma unroll
                for (int m = 0; m < 2; ++m) {
                    p0 += fmaxf(c[m][nt][0]+bh0, 0.f) + fmaxf(c[m][nt][2]+bh0, 0.f);
                    p1 += fmaxf(c[m][nt][1]+bh1, 0.f) + fmaxf(c[m][nt][3]+bh1, 0.f);
                }
                #pragma unroll
                for (int off = 4; off < 32; off <<= 1) {
                    p0 += __shfl_xor_sync(0xffffffffu, p0, off);
                    p1 += __shfl_xor_sync(0xffffffffu, p1, off);
                }
                if (lane < 4) {
                    atomicAdd(&s_red[n0],   p0);
                    atomicAdd(&s_red[n0+1], p1);
                }
            }
        }
        __syncthreads();
        if (tid < 128) g_m[(size_t)tb*HD_ + tid] = s_red[tid] * (1.0f/(float)V_);
        __syncthreads();
    }
}

// ---------------- K4a: cumsum over t ------------------------------------------------------
__global__ void k4a_cumsum() {
    int gid = blockIdx.x * 1024 + threadIdx.x;
    int b = gid >> 7, h = gid & 127;
    float run = 0.f;
    for (int t = 0; t < T_; ++t) {
        size_t idx = ((size_t)t*B_ + b)*HD_ + h;
        run += g_m[idx];
        g_m[idx] = run;
    }
}

// ---------------- K4b: gi = cum @ Wih^T + bih ---------------------------------------------
__global__ __launch_bounds__(384) void k4b_gi(const float* __restrict__ Wih, const float* __restrict__ bih) {
    __shared__ float s_c[128];
    int tb = blockIdx.x, tid = threadIdx.x;
    if (tid < 128) s_c[tid] = g_m[(size_t)tb*HD_ + tid];
    __syncthreads();
    float a0 = bih[tid], a1 = 0.f, a2 = 0.f, a3 = 0.f;
    const float* wr = Wih + (size_t)tid*HD_;
    #pragma unroll 8
    for (int k = 0; k < HD_; k += 4) {
        a0 = fmaf(s_c[k  ], wr[k  ], a0);
        a1 = fmaf(s_c[k+1], wr[k+1], a1);
        a2 = fmaf(s_c[k+2], wr[k+2], a2);
        a3 = fmaf(s_c[k+3], wr[k+3], a3);
    }
    g_gi[(size_t)tb*3*HD_ + tid] = (a0+a1)+(a2+a3);
}

// ---------------- K5: GRU (batch 16 only) -------------------------------------------------
__global__ __launch_bounds__(384) void k5_gru(const float* __restrict__ Whh, const float* __restrict__ bhh) {
    extern __shared__ float sm[];
    float* s_W  = sm;
    float* s_h  = sm + 384*129;
    float* s_gh = s_h + 128;
    int b = blockIdx.x, tid = threadIdx.x;
    for (int idx = tid; idx < 384*HD_; idx += 384) {
        int g = idx >> 7, k = idx & 127;
        s_W[g*129 + k] = Whh[idx];
    }
    float bh = bhh[tid];
    if (tid < 128) s_h[tid] = 0.f;
    __syncthreads();
    const float* wr = s_W + tid*129;
    for (int t = 0; t < T_; ++t) {
        float a0 = bh, a1 = 0.f, a2 = 0.f, a3 = 0.f;
        #pragma unroll 8
        for (int k = 0; k < HD_; k += 4) {
            a0 = fmaf(s_h[k  ], wr[k  ], a0);
            a1 = fmaf(s_h[k+1], wr[k+1], a1);
            a2 = fmaf(s_h[k+2], wr[k+2], a2);
            a3 = fmaf(s_h[k+3], wr[k+3], a3);
        }
        s_gh[tid] = (a0+a1)+(a2+a3);
        __syncthreads();
        if (tid < 128) {
            size_t row = ((size_t)t*B_ + b)*3*HD_;
            float r  = 1.f/(1.f + expf(-(g_gi[row +        tid] + s_gh[tid])));
            float z  = 1.f/(1.f + expf(-(g_gi[row + HD_ +  tid] + s_gh[HD_ + tid])));
            float nn = tanhf(g_gi[row + 2*HD_ + tid] + r*s_gh[2*HD_ + tid]);
            float hp = s_h[tid];
            float hv = (1.f - z)*nn + z*hp;
            s_h[tid] = hv;
            g_y[((size_t)t*B_ + b)*HD_ + tid] = hv;
        }
        __syncthreads();
    }
}

// ---------------- K6: output projection + HN broadcast ------------------------------------
__global__ __launch_bounds__(256) void k6_out(const float* __restrict__ Wo, const float* __restrict__ bo,
                                              float* __restrict__ out) {
    __shared__ float s_y[128];
    __shared__ float s_o[64];
    int bt = blockIdx.x;
    int b = bt >> 5, t = bt & 31;
    int tid = threadIdx.x;
    if (tid < 128) s_y[tid] = g_y[((size_t)t*B_ + b)*HD_ + tid];
    __syncthreads();
    if (tid < DOUT_) {
        float a0 = bo[tid], a1 = 0.f, a2 = 0.f, a3 = 0.f;
        #pragma unroll 8
        for (int h = 0; h < HD_; h += 4) {
            a0 = fmaf(s_y[h  ], Wo[(h  )*DOUT_ + tid], a0);
            a1 = fmaf(s_y[h+1], Wo[(h+1)*DOUT_ + tid], a1);
            a2 = fmaf(s_y[h+2], Wo[(h+2)*DOUT_ + tid], a2);
            a3 = fmaf(s_y[h+3], Wo[(h+3)*DOUT_ + tid], a3);
        }
        s_o[tid] = (a0+a1)+(a2+a3);
    }
    __syncthreads();
    for (int idx = tid; idx < HN_*DOUT_; idx += 256) {
        int hn = idx >> 6, d = idx & 63;
        out[(((size_t)b*HN_ + hn)*T_ + t)*DOUT_ + d] = s_o[d];
    }
}

// ---------------- launch ------------------------------------------------------------------
extern "C" void kernel_launch(void* const* d_in, const int* in_sizes, int n_in,
                              void* d_out, int out_size) {
    const float* x   = (const float*)d_in[0];
    const float* adj = (const float*)d_in[1];
    const float* Wp  = (const float*)d_in[2];
    const float* bp  = (const float*)d_in[3];
    const float* W1  = (const float*)d_in[4];
    const float* b1  = (const float*)d_in[5];
    const float* W2  = (const float*)d_in[6];
    const float* b2  = (const float*)d_in[7];
    const float* Wn1 = (const float*)d_in[8];
    const float* bn1 = (const float*)d_in[9];
    const float* Wn2 = (const float*)d_in[10];
    const float* bn2 = (const float*)d_in[11];
    const float* Wih = (const float*)d_in[12];
    const float* Whh = (const float*)d_in[13];
    const float* bih = (const float*)d_in[14];
    const float* bhh = (const float*)d_in[15];
    const float* Wo  = (const float*)d_in[16];
    const float* bo  = (const float*)d_in[17];
    float* out = (float*)d_out;

    size_t smem1 = (size_t)(16384 + 64) * sizeof(float);
    size_t smem3 = (size_t)(6 * 128 * WS * 2 + (128*3) * 4);     // 210,432 B
    size_t smem5 = (size_t)(384*129 + 128 + 384) * sizeof(float);

    cudaFuncSetAttribute(k1_aibj,     cudaFuncAttributeMaxDynamicSharedMemorySize, (int)smem1);
    cudaFuncSetAttribute(k3_node_mma, cudaFuncAttributeMaxDynamicSharedMemorySize, (int)smem3);
    cudaFuncSetAttribute(k5_gru,      cudaFuncAttributeMaxDynamicSharedMemorySize, (int)smem5);

    k0_prep    <<<DIN_ + 1, 256>>>(Wp, bp, W1, b1);
    k1_aibj    <<<NTB, 256, smem1>>>(x);
    k2_edge_mma<<<K2GRID, 512>>>(adj, W2, b2);
    k3_node_mma<<<K3GRID, 512, smem3>>>(Wn1, bn1, Wn2, bn2);
    k4a_cumsum <<<2, 1024>>>();
    k4b_gi     <<<NTB, 384>>>(Wih, bih);
    k5_gru     <<<B_, 384, smem5>>>(Whh, bhh);
    k6_out     <<<B_*T_, 256>>>(Wo, bo, out);
}